// round 11
// baseline (speedup 1.0000x reference)
#include <cuda_runtime.h>
#include <math.h>
#include <stdint.h>
#include <mma.h>

using namespace nvcuda;

// ---------------- problem constants ----------------
#define D_DIM   1024
#define F_DIM   704
#define E_NUM   64
#define NTOK    1024
#define TOPK    6
#define FS_DIM  1408
#define NPAIR   (NTOK*TOPK)

// ---------------- scratch (static device arrays) ----------------
__device__ float g_hbuf[NPAIR * F_DIM];
__device__ float g_dbuf[NPAIR * D_DIM];
__device__ float g_sh[NTOK * FS_DIM];
__device__ int   g_count[E_NUM];
__device__ int   g_offset[E_NUM];
__device__ int   g_cursor[E_NUM];
__device__ int   g_tok_expert[NTOK*TOPK];
__device__ float g_tok_w[NTOK*TOPK];
__device__ int   g_tok_pair[NTOK*TOPK];
__device__ int   g_pair_token[NPAIR];
__device__ float g_pair_w[NPAIR];
__device__ float g_scores_scratch[NTOK * E_NUM];

// ---------------- smem geometry (float units) ----------------
#define LDA 36
#define LDB 68
#define LDC 68
// up kernel: stage = A(128x36=4608) + B1(32x68=2176) + B2(2176) = 8960 floats
#define STG_UP      8960
#define STOK_UP     (3*STG_UP)            // 26880
#define SMEM_UP_B   ((STOK_UP + 128) * 4) // 108032 bytes
// down kernel: stage = A(4608) + B(2176) = 6784 floats
#define STG_DN      6784
#define SMEM_DN_B   (3*STG_DN*4)          // 81408 bytes

// ---------------- cp.async helpers ----------------
__device__ __forceinline__ void cp16(uint32_t s, const void* g) {
    asm volatile("cp.async.cg.shared.global [%0], [%1], 16;" :: "r"(s), "l"(g));
}
__device__ __forceinline__ void cp_commit() {
    asm volatile("cp.async.commit_group;" ::: "memory");
}
template<int N> __device__ __forceinline__ void cp_wait() {
    asm volatile("cp.async.wait_group %0;" :: "n"(N) : "memory");
}

// ---------------- WMMA tf32 helpers ----------------
using FragA = wmma::fragment<wmma::matrix_a, 16, 16, 8, wmma::precision::tf32, wmma::row_major>;
using FragB = wmma::fragment<wmma::matrix_b, 16, 16, 8, wmma::precision::tf32, wmma::row_major>;
using FragC = wmma::fragment<wmma::accumulator, 16, 16, 8, float>;

__device__ __forceinline__ void cvt_a(FragA& f) {
    #pragma unroll
    for (int i = 0; i < f.num_elements; i++) f.x[i] = wmma::__float_to_tf32(f.x[i]);
}
__device__ __forceinline__ void cvt_b(FragB& f) {
    #pragma unroll
    for (int i = 0; i < f.num_elements; i++) f.x[i] = wmma::__float_to_tf32(f.x[i]);
}

// ---------------- small kernels ----------------
__global__ void init_kernel() {
    int i = threadIdx.x;
    if (i < E_NUM) { g_count[i] = 0; g_cursor[i] = 0; }
}

__global__ void gate_kernel(const float* __restrict__ x,
                            const float* __restrict__ wg,
                            const float* __restrict__ gb,
                            float* __restrict__ scores_out) {
    __shared__ float xs[D_DIM];
    __shared__ float sc[E_NUM];
    int t = blockIdx.x;
    int tid = threadIdx.x;

    const float4* xv = (const float4*)(x + (size_t)t * D_DIM);
    float4* xsv = (float4*)xs;
    for (int i = tid; i < D_DIM/4; i += 128) xsv[i] = xv[i];
    __syncthreads();

    if (tid < E_NUM) {
        const float4* wv = (const float4*)(wg + (size_t)tid * D_DIM);
        float acc = 0.f;
        #pragma unroll 8
        for (int i = 0; i < D_DIM/4; i++) {
            float4 a = xsv[i]; float4 b = wv[i];
            acc += a.x*b.x + a.y*b.y + a.z*b.z + a.w*b.w;
        }
        float s = 1.f/(1.f + expf(-acc)) + gb[tid];
        sc[tid] = s;
        scores_out[(size_t)t * E_NUM + tid] = s;
    }
    __syncthreads();

    if (tid == 0) {
        float tmp[E_NUM];
        for (int i = 0; i < E_NUM; i++) tmp[i] = sc[i];
        int   sel[TOPK]; float selw[TOPK];
        float wsum = 0.f;
        for (int k = 0; k < TOPK; k++) {
            int bi = 0; float bv = tmp[0];
            for (int i = 1; i < E_NUM; i++)
                if (tmp[i] > bv) { bv = tmp[i]; bi = i; }
            sel[k] = bi; selw[k] = bv; wsum += bv;
            tmp[bi] = -1e30f;
        }
        float inv = 1.f / wsum;
        for (int k = 0; k < TOPK; k++) {
            int e = sel[k];
            g_tok_expert[t*TOPK + k] = e;
            g_tok_w[t*TOPK + k] = selw[k] * inv;
            atomicAdd(&g_count[e], 1);
        }
    }
}

// one block, 1024 threads: prefix-scan counts then bucket-assign
__global__ void scan_assign_kernel() {
    if (threadIdx.x == 0) {
        int acc = 0;
        for (int e = 0; e < E_NUM; e++) { g_offset[e] = acc; acc += g_count[e]; }
    }
    __syncthreads();
    int t = threadIdx.x;
    #pragma unroll
    for (int k = 0; k < TOPK; k++) {
        int e = g_tok_expert[t*TOPK + k];
        int slot = atomicAdd(&g_cursor[e], 1);
        int p = g_offset[e] + slot;
        g_pair_token[p] = t;
        g_pair_w[p] = g_tok_w[t*TOPK + k];
        g_tok_pair[t*TOPK + k] = p;
    }
}

// ===========================================================================
// Fused up-proj: routed experts (y<64) and shared expert (y==64).
// C = silu(A@B1) * (A@B3); routed -> g_hbuf (masked), shared -> g_sh.
// 3-stage cp.async, one barrier per K-chunk. grid (22, 65, 8), 256 threads.
// ===========================================================================
__global__ void __launch_bounds__(256)
up_fused(const float* __restrict__ x,
         const float* __restrict__ w1r,
         const float* __restrict__ w3r,
         const float* __restrict__ w1s,
         const float* __restrict__ w3s) {
    extern __shared__ float sm[];
    const int tid = threadIdx.x;
    const int y = blockIdx.y;
    const bool se = (y == E_NUM);
    const int f0 = blockIdx.x * 64;
    const int row0 = blockIdx.z * 128;

    int cnt, base, ldB, ldD;
    const float *B1, *B2;
    float* dstbuf;
    if (se) {
        cnt = NTOK; base = 0;
        B1 = w1s; B2 = w3s; ldB = FS_DIM;
        dstbuf = g_sh; ldD = FS_DIM;
    } else {
        if (f0 >= F_DIM) return;
        cnt = g_count[y];
        if (row0 >= cnt) return;
        base = g_offset[y];
        B1 = w1r + (size_t)y * D_DIM * F_DIM;
        B2 = w3r + (size_t)y * D_DIM * F_DIM;
        ldB = F_DIM;
        dstbuf = g_hbuf; ldD = F_DIM;
    }

    int* toks = (int*)(sm + STOK_UP);
    if (tid < 128) {
        int r = row0 + tid;
        if (se) toks[tid] = r;
        else    toks[tid] = (r < cnt) ? g_pair_token[base + r] : 0;
    }
    __syncthreads();

    const int c4a = tid & 7;
    const int arow = tid >> 3;
    const int bc4 = tid & 15;
    const int brow = tid >> 4;

    const float4* ar[4];
    uint32_t a_off[4];
    #pragma unroll
    for (int i = 0; i < 4; i++) {
        ar[i] = (const float4*)(x + (size_t)toks[arow + i*32] * D_DIM);
        a_off[i] = (uint32_t)(((arow + i*32) * LDA + c4a*4) * 4);
    }
    uint32_t b_off[2];
    #pragma unroll
    for (int i = 0; i < 2; i++)
        b_off[i] = (uint32_t)(((brow + i*16) * LDB + bc4*4) * 4);

    uint32_t sbase = (uint32_t)__cvta_generic_to_shared(sm);

    const int wid = tid >> 5;
    const int warpM = wid >> 1, warpN = wid & 1;

    FragC c1[2][2], c3[2][2];
    #pragma unroll
    for (int mi = 0; mi < 2; mi++)
        #pragma unroll
        for (int ni = 0; ni < 2; ni++) {
            wmma::fill_fragment(c1[mi][ni], 0.f);
            wmma::fill_fragment(c3[mi][ni], 0.f);
        }

    const int nchunk = D_DIM / 32;

    #define ISSUE_UP(kc) do { \
        const int k0_ = (kc) * 32; \
        const uint32_t st_ = sbase + (uint32_t)(((kc) % 3) * STG_UP * 4); \
        _Pragma("unroll") \
        for (int i_ = 0; i_ < 4; i_++) \
            cp16(st_ + a_off[i_], ar[i_] + (k0_ >> 2) + c4a); \
        const uint32_t sb1_ = st_ + 4608u*4u; \
        const uint32_t sb2_ = st_ + 6784u*4u; \
        _Pragma("unroll") \
        for (int i_ = 0; i_ < 2; i_++) { \
            cp16(sb1_ + b_off[i_], B1 + (size_t)(k0_ + brow + i_*16) * ldB + f0 + bc4*4); \
            cp16(sb2_ + b_off[i_], B2 + (size_t)(k0_ + brow + i_*16) * ldB + f0 + bc4*4); \
        } \
        cp_commit(); \
    } while (0)

    ISSUE_UP(0);
    ISSUE_UP(1);
    for (int kc = 0; kc < nchunk; kc++) {
        if (kc == nchunk - 1) cp_wait<0>();
        else                  cp_wait<1>();
        __syncthreads();                 // stage kc visible; all warps past kc-1
        if (kc + 2 < nchunk) ISSUE_UP(kc + 2);   // overwrites stage (kc-1)%3: safe

        const float* St  = sm + (kc % 3) * STG_UP;
        const float* As  = St;
        const float* B1s = St + 4608;
        const float* B2s = St + 6784;
        #pragma unroll
        for (int ks = 0; ks < 4; ks++) {
            FragA a[2];
            #pragma unroll
            for (int mi = 0; mi < 2; mi++) {
                wmma::load_matrix_sync(a[mi], As + (warpM*32 + mi*16) * LDA + ks*8, LDA);
                cvt_a(a[mi]);
            }
            FragB b;
            #pragma unroll
            for (int ni = 0; ni < 2; ni++) {
                wmma::load_matrix_sync(b, B1s + (ks*8) * LDB + warpN*32 + ni*16, LDB);
                cvt_b(b);
                #pragma unroll
                for (int mi = 0; mi < 2; mi++)
                    wmma::mma_sync(c1[mi][ni], a[mi], b, c1[mi][ni]);
                wmma::load_matrix_sync(b, B2s + (ks*8) * LDB + warpN*32 + ni*16, LDB);
                cvt_b(b);
                #pragma unroll
                for (int mi = 0; mi < 2; mi++)
                    wmma::mma_sync(c3[mi][ni], a[mi], b, c3[mi][ni]);
            }
        }
    }
    #undef ISSUE_UP
    __syncthreads();   // all MMAs done before C tile overwrites stage buffers

    float* Cs = sm;
    #pragma unroll
    for (int mi = 0; mi < 2; mi++)
        #pragma unroll
        for (int ni = 0; ni < 2; ni++) {
            #pragma unroll
            for (int k = 0; k < c1[mi][ni].num_elements; k++) {
                float v1 = c1[mi][ni].x[k], v3 = c3[mi][ni].x[k];
                c1[mi][ni].x[k] = v1 / (1.f + expf(-v1)) * v3;
            }
            wmma::store_matrix_sync(Cs + (warpM*32 + mi*16) * LDC + warpN*32 + ni*16,
                                    c1[mi][ni], LDC, wmma::mem_row_major);
        }
    __syncthreads();

    int valid = cnt - row0; if (valid > 128) valid = 128;
    #pragma unroll
    for (int i = 0; i < 8; i++) {
        int lin = tid + i * 256;
        int row = lin >> 4, cc = lin & 15;
        if (row < valid) {
            float4 v = *(float4*)(Cs + row * LDC + cc * 4);
            *(float4*)(dstbuf + (size_t)(base + row0 + row) * ldD + f0 + cc * 4) = v;
        }
    }
}

// ===========================================================================
// Fused down-proj: routed (y<64, A=g_hbuf, K=F_DIM, dst=g_dbuf)
//                  shared (y==64, A=g_sh, K=FS_DIM, dst=out).
// grid (16, 65, 8), 256 threads. 3-stage cp.async, one barrier per chunk.
// ===========================================================================
__global__ void __launch_bounds__(256)
down_fused(const float* __restrict__ w2r,
           const float* __restrict__ w2s,
           float* __restrict__ out) {
    extern __shared__ float sm[];
    const int tid = threadIdx.x;
    const int y = blockIdx.y;
    const bool se = (y == E_NUM);
    const int d0 = blockIdx.x * 64;
    const int row0 = blockIdx.z * 128;

    int cnt, base, nchunk;
    const float* B1;
    const float* Abase;
    int ldA;
    float* dstbuf;
    if (se) {
        cnt = NTOK; base = 0;
        B1 = w2s; nchunk = FS_DIM / 32;
        Abase = g_sh; ldA = FS_DIM;
        dstbuf = out;
    } else {
        cnt = g_count[y];
        if (row0 >= cnt) return;
        base = g_offset[y];
        B1 = w2r + (size_t)y * F_DIM * D_DIM;
        nchunk = F_DIM / 32;
        Abase = g_hbuf; ldA = F_DIM;
        dstbuf = g_dbuf;
    }

    const int c4a = tid & 7;
    const int arow = tid >> 3;
    const int bc4 = tid & 15;
    const int brow = tid >> 4;

    const float4* ar[4];
    uint32_t a_off[4];
    #pragma unroll
    for (int i = 0; i < 4; i++) {
        int r = row0 + arow + i*32;
        int rr = (r < cnt) ? r : (cnt - 1);
        ar[i] = (const float4*)(Abase + (size_t)(base + rr) * ldA);
        a_off[i] = (uint32_t)(((arow + i*32) * LDA + c4a*4) * 4);
    }
    uint32_t b_off[2];
    #pragma unroll
    for (int i = 0; i < 2; i++)
        b_off[i] = (uint32_t)(((brow + i*16) * LDB + bc4*4) * 4);

    uint32_t sbase = (uint32_t)__cvta_generic_to_shared(sm);

    const int wid = tid >> 5;
    const int warpM = wid >> 1, warpN = wid & 1;

    FragC c[2][2];
    #pragma unroll
    for (int mi = 0; mi < 2; mi++)
        #pragma unroll
        for (int ni = 0; ni < 2; ni++)
            wmma::fill_fragment(c[mi][ni], 0.f);

    #define ISSUE_DN(kc) do { \
        const int k0_ = (kc) * 32; \
        const uint32_t st_ = sbase + (uint32_t)(((kc) % 3) * STG_DN * 4); \
        _Pragma("unroll") \
        for (int i_ = 0; i_ < 4; i_++) \
            cp16(st_ + a_off[i_], ar[i_] + (k0_ >> 2) + c4a); \
        const uint32_t sb1_ = st_ + 4608u*4u; \
        _Pragma("unroll") \
        for (int i_ = 0; i_ < 2; i_++) \
            cp16(sb1_ + b_off[i_], B1 + (size_t)(k0_ + brow + i_*16) * D_DIM + d0 + bc4*4); \
        cp_commit(); \
    } while (0)

    ISSUE_DN(0);
    ISSUE_DN(1);
    for (int kc = 0; kc < nchunk; kc++) {
        if (kc == nchunk - 1) cp_wait<0>();
        else                  cp_wait<1>();
        __syncthreads();
        if (kc + 2 < nchunk) ISSUE_DN(kc + 2);

        const float* St  = sm + (kc % 3) * STG_DN;
        const float* As  = St;
        const float* B1s = St + 4608;
        #pragma unroll
        for (int ks = 0; ks < 4; ks++) {
            FragA a[2];
            #pragma unroll
            for (int mi = 0; mi < 2; mi++) {
                wmma::load_matrix_sync(a[mi], As + (warpM*32 + mi*16) * LDA + ks*8, LDA);
                cvt_a(a[mi]);
            }
            #pragma unroll
            for (int ni = 0; ni < 2; ni++) {
                FragB b;
                wmma::load_matrix_sync(b, B1s + (ks*8) * LDB + warpN*32 + ni*16, LDB);
                cvt_b(b);
                #pragma unroll
                for (int mi = 0; mi < 2; mi++)
                    wmma::mma_sync(c[mi][ni], a[mi], b, c[mi][ni]);
            }
        }
    }
    #undef ISSUE_DN
    __syncthreads();   // mainloop fully drained before C overwrites stages

    float* Cs = sm;
    #pragma unroll
    for (int mi = 0; mi < 2; mi++)
        #pragma unroll
        for (int ni = 0; ni < 2; ni++)
            wmma::store_matrix_sync(Cs + (warpM*32 + mi*16) * LDC + warpN*32 + ni*16,
                                    c[mi][ni], LDC, wmma::mem_row_major);
    __syncthreads();

    int valid = cnt - row0; if (valid > 128) valid = 128;
    #pragma unroll
    for (int i = 0; i < 8; i++) {
        int lin = tid + i * 256;
        int row = lin >> 4, cc = lin & 15;
        if (row < valid) {
            float4 v = *(float4*)(Cs + row * LDC + cc * 4);
            *(float4*)(dstbuf + (size_t)(base + row0 + row) * D_DIM + d0 + cc * 4) = v;
        }
    }
}

// ---------------- combine (applies gate weights) ----------------
__global__ void combine_kernel(float* __restrict__ out) {
    int t = blockIdx.x;
    __shared__ int p[TOPK];
    __shared__ float w[TOPK];
    if (threadIdx.x < TOPK) {
        p[threadIdx.x] = g_tok_pair[t*TOPK + threadIdx.x];
        w[threadIdx.x] = g_tok_w[t*TOPK + threadIdx.x];
    }
    __syncthreads();
    int d = threadIdx.x * 4;
    float4 s = *(float4*)(out + (size_t)t * D_DIM + d);
    #pragma unroll
    for (int k = 0; k < TOPK; k++) {
        const float4 v = *(const float4*)(g_dbuf + (size_t)p[k] * D_DIM + d);
        float wk = w[k];
        s.x += wk*v.x; s.y += wk*v.y; s.z += wk*v.z; s.w += wk*v.w;
    }
    *(float4*)(out + (size_t)t * D_DIM + d) = s;
}

// ---------------------------------------------------------------------------
extern "C" void kernel_launch(void* const* d_in, const int* in_sizes, int n_in,
                              void* d_out, int out_size) {
    const float* x   = (const float*)d_in[0];
    const float* wg  = (const float*)d_in[1];
    const float* gb  = (const float*)d_in[2];
    const float* w1s = (const float*)d_in[3];
    const float* w2s = (const float*)d_in[4];
    const float* w3s = (const float*)d_in[5];
    const float* w1r = (const float*)d_in[6];
    const float* w2r = (const float*)d_in[7];
    const float* w3r = (const float*)d_in[8];
    float* out = (float*)d_out;

    float* scores;
    if (out_size >= NTOK*D_DIM + NTOK*E_NUM) {
        scores = out + (size_t)NTOK * D_DIM;
    } else {
        cudaGetSymbolAddress((void**)&scores, g_scores_scratch);
    }

    static int attr_done = 0;
    if (!attr_done) {
        cudaFuncSetAttribute(up_fused,   cudaFuncAttributeMaxDynamicSharedMemorySize, SMEM_UP_B);
        cudaFuncSetAttribute(down_fused, cudaFuncAttributeMaxDynamicSharedMemorySize, SMEM_DN_B);
        attr_done = 1;
    }

    init_kernel<<<1, 64>>>();
    gate_kernel<<<NTOK, 128>>>(x, wg, gb, scores);
    scan_assign_kernel<<<1, NTOK>>>();

    up_fused<<<dim3(FS_DIM/64, E_NUM + 1, 8), 256, SMEM_UP_B>>>(x, w1r, w3r, w1s, w3s);
    down_fused<<<dim3(D_DIM/64, E_NUM + 1, 8), 256, SMEM_DN_B>>>(w2r, w2s, out);

    combine_kernel<<<NTOK, 256>>>(out);
}